// round 3
// baseline (speedup 1.0000x reference)
#include <cuda_runtime.h>
#include <cstdint>
#include <math.h>

// Problem constants (fixed by dataset)
#define NMAX   25000
#define EMAX   400000
#define GMAX   1000
#define HID    185
#define INCH   9
#define JKDIM  (4*HID)   // 740

// ---------------- scratch (device globals, no allocation) ----------------
__device__ float    g_dis[NMAX];            // deg -> rsqrt(deg)
__device__ int      g_cnt[NMAX];
__device__ int      g_offs[NMAX + 1];
__device__ int      g_cursor[NMAX];
__device__ int      g_csr_src[EMAX];
__device__ float    g_csr_w[EMAX];
__device__ float    g_ax[NMAX * INCH];
__device__ float    g_xs[NMAX * JKDIM];     // concat buffer [N,740]
__device__ float    g_tmp[NMAX * HID];
__device__ float    g_hjk[NMAX * HID];
__device__ unsigned g_pool[GMAX * HID];
__device__ float    g_bnscale[4 * HID];
__device__ float    g_bnshift[4 * HID];

// ---------------- helpers ----------------
__device__ __forceinline__ unsigned enc_f(float f) {
    unsigned u = __float_as_uint(f);
    return (u & 0x80000000u) ? ~u : (u | 0x80000000u);
}
__device__ __forceinline__ float dec_f(unsigned e) {
    return (e & 0x80000000u) ? __uint_as_float(e & 0x7FFFFFFFu)
                             : __uint_as_float(~e);
}
__device__ __forceinline__ void split_tf32(float v, uint32_t& h, uint32_t& l) {
    asm("cvt.rna.tf32.f32 %0, %1;" : "=r"(h) : "f"(v));
    float r = v - __uint_as_float(h);
    asm("cvt.rna.tf32.f32 %0, %1;" : "=r"(l) : "f"(r));
}
__device__ __forceinline__ void mma8(float* c, const uint32_t* a, const uint32_t* b) {
    asm volatile("mma.sync.aligned.m16n8k8.row.col.f32.tf32.tf32.f32 "
        "{%0,%1,%2,%3}, {%4,%5,%6,%7}, {%8,%9}, {%0,%1,%2,%3};"
        : "+f"(c[0]), "+f"(c[1]), "+f"(c[2]), "+f"(c[3])
        : "r"(a[0]), "r"(a[1]), "r"(a[2]), "r"(a[3]), "r"(b[0]), "r"(b[1]));
}

// ---------------- graph preprocessing ----------------
__global__ void k_init(int N, int G) {
    int i = blockIdx.x * blockDim.x + threadIdx.x;
    if (i < N) { g_dis[i] = 1.0f; g_cnt[i] = 0; }
    if (i < G * HID) g_pool[i] = 0x007FFFFFu;   // enc(-inf)
}

__global__ void k_count(const int* __restrict__ ei, int E) {
    int e = blockIdx.x * blockDim.x + threadIdx.x;
    if (e >= E) return;
    int d = ei[E + e];
    atomicAdd(&g_dis[d], 1.0f);
    atomicAdd(&g_cnt[d], 1);
}

__global__ void k_rsqrt_deg(int N) {
    int i = blockIdx.x * blockDim.x + threadIdx.x;
    if (i < N) g_dis[i] = rsqrtf(g_dis[i]);
}

// single-block scan of g_cnt -> g_offs (exclusive), offs[N] = total
__global__ void k_scan(int N) {
    __shared__ int sums[1024];
    int t = threadIdx.x;
    int chunk = (N + 1023) / 1024;
    int s = t * chunk;
    int e = min(s + chunk, N);
    int acc = 0;
    for (int i = s; i < e; i++) acc += g_cnt[i];
    sums[t] = acc;
    __syncthreads();
    for (int off = 1; off < 1024; off <<= 1) {
        int add = (t >= off) ? sums[t - off] : 0;
        __syncthreads();
        sums[t] += add;
        __syncthreads();
    }
    int run = (t == 0) ? 0 : sums[t - 1];
    for (int i = s; i < e; i++) { g_offs[i] = run; run += g_cnt[i]; }
    if (s < N && e == N) g_offs[N] = run;
}

__global__ void k_cursor(int N) {
    int i = blockIdx.x * blockDim.x + threadIdx.x;
    if (i < N) g_cursor[i] = g_offs[i];
}

__global__ void k_fill(const int* __restrict__ ei, int E) {
    int e = blockIdx.x * blockDim.x + threadIdx.x;
    if (e >= E) return;
    int s = ei[e];
    int d = ei[E + e];
    int p = atomicAdd(&g_cursor[d], 1);
    g_csr_src[p] = s;
    g_csr_w[p]   = g_dis[s];
}

// aggregate raw x (9 channels): warp per node
__global__ void k_aggregate_x(const float* __restrict__ x, int N) {
    int warp = (blockIdx.x * blockDim.x + threadIdx.x) >> 5;
    int lane = threadIdx.x & 31;
    if (warp >= N) return;
    int n = warp;
    int s0 = g_offs[n], s1 = g_offs[n + 1];
    float acc[INCH];
#pragma unroll
    for (int c = 0; c < INCH; c++) acc[c] = 0.f;
    for (int e = s0 + lane; e < s1; e += 32) {
        int s = g_csr_src[e];
        float w = g_csr_w[e];
#pragma unroll
        for (int c = 0; c < INCH; c++) acc[c] += w * x[s * INCH + c];
    }
#pragma unroll
    for (int c = 0; c < INCH; c++)
#pragma unroll
        for (int o = 16; o; o >>= 1)
            acc[c] += __shfl_xor_sync(0xffffffffu, acc[c], o);
    if (lane == 0) {
        float dn = g_dis[n];
#pragma unroll
        for (int c = 0; c < INCH; c++)
            g_ax[n * INCH + c] = dn * acc[c] + dn * dn * x[n * INCH + c];
    }
}

__global__ void k_bn_pre(const float* __restrict__ gamma, const float* __restrict__ beta,
                         const float* __restrict__ mean, const float* __restrict__ var) {
    int i = blockIdx.x * blockDim.x + threadIdx.x;
    if (i < 4 * HID) {
        float sc = gamma[i] * rsqrtf(var[i] + 1e-5f);
        g_bnscale[i] = sc;
        g_bnshift[i] = beta[i] - mean[i] * sc;
    }
}

// ---------------- tf32x2 tensor-core GEMM ----------------
// C[Nrows, Mout] = A[Nrows, K] @ B[K, Mout] (+epilogue)
// CTA tile 128x64, warp tile 32x32, BK = 32.
// mode 0: plain store, mode 1: +bias, mode 2: +bias then bn scale/shift + relu
__global__ void __launch_bounds__(256)
k_mma(const float* __restrict__ A, int lda,
      const float* __restrict__ B, int ldb,
      float* __restrict__ C, int ldc,
      int Nrows, int Kreal, int Mout,
      const float* __restrict__ bias,
      const float* __restrict__ scale,
      const float* __restrict__ shift,
      int mode) {
    __shared__ float As[128][36];   // row-major, stride 36: conflict-free
    __shared__ float Bs[32][72];    // k-major,  stride 72: conflict-free

    int tid = threadIdx.x;
    int lane = tid & 31;
    int w = tid >> 5;
    int wm = w & 3;          // 4 warp-rows of 32
    int wn = w >> 2;         // 2 warp-cols of 32
    int rowBase = blockIdx.y * 128;
    int colBase = blockIdx.x * 64;

    float acc[2][4][4];
#pragma unroll
    for (int i = 0; i < 2; i++)
#pragma unroll
        for (int j = 0; j < 4; j++)
#pragma unroll
            for (int q = 0; q < 4; q++) acc[i][j][q] = 0.f;

    int KC = (Kreal + 31) >> 5;
    for (int kt = 0; kt < KC; kt++) {
        int k0 = kt * 32;
        // load A tile: 128 rows x 32 k (coalesced: 32 consecutive k per row)
        {
            int kk = lane;
            int gk = k0 + kk;
            bool kok = (gk < Kreal);
#pragma unroll 4
            for (int rr = w; rr < 128; rr += 8) {
                int gr = rowBase + rr;
                float v = (gr < Nrows && kok) ? A[(size_t)gr * lda + gk] : 0.f;
                As[rr][kk] = v;
            }
        }
        // load B tile: 32 k x 64 cols (coalesced over cols)
        for (int i = tid; i < 2048; i += 256) {
            int kk = i >> 6, nn = i & 63;
            int gk = k0 + kk, gn = colBase + nn;
            float v = (gk < Kreal && gn < Mout) ? B[(size_t)gk * ldb + gn] : 0.f;
            Bs[kk][nn] = v;
        }
        __syncthreads();

#pragma unroll
        for (int ks = 0; ks < 4; ks++) {
            // B fragments (4 n-frags of 8 cols each), split hi/lo
            uint32_t bh[4][2], bl[4][2];
#pragma unroll
            for (int nf = 0; nf < 4; nf++) {
                int nn = wn * 32 + nf * 8 + (lane >> 2);
                float v0 = Bs[ks * 8 + (lane & 3)][nn];
                float v1 = Bs[ks * 8 + (lane & 3) + 4][nn];
                split_tf32(v0, bh[nf][0], bl[nf][0]);
                split_tf32(v1, bh[nf][1], bl[nf][1]);
            }
#pragma unroll
            for (int mf = 0; mf < 2; mf++) {
                int r0 = wm * 32 + mf * 16 + (lane >> 2);
                int c0 = ks * 8 + (lane & 3);
                float a0 = As[r0][c0];
                float a1 = As[r0 + 8][c0];
                float a2 = As[r0][c0 + 4];
                float a3 = As[r0 + 8][c0 + 4];
                uint32_t ah[4], al[4];
                split_tf32(a0, ah[0], al[0]);
                split_tf32(a1, ah[1], al[1]);
                split_tf32(a2, ah[2], al[2]);
                split_tf32(a3, ah[3], al[3]);
#pragma unroll
                for (int nf = 0; nf < 4; nf++) {
                    mma8(acc[mf][nf], ah, bh[nf]);
                    mma8(acc[mf][nf], ah, bl[nf]);
                    mma8(acc[mf][nf], al, bh[nf]);
                }
            }
        }
        __syncthreads();
    }

    // epilogue
#pragma unroll
    for (int mf = 0; mf < 2; mf++) {
#pragma unroll
        for (int nf = 0; nf < 4; nf++) {
            int rbase = rowBase + wm * 32 + mf * 16 + (lane >> 2);
            int cbase = colBase + wn * 32 + nf * 8 + (lane & 3) * 2;
#pragma unroll
            for (int q = 0; q < 4; q++) {
                int r = rbase + ((q >= 2) ? 8 : 0);
                int c = cbase + (q & 1);
                if (r >= Nrows || c >= Mout) continue;
                float v = acc[mf][nf][q];
                if (mode >= 1) v += bias[c];
                if (mode == 2) v = fmaxf(fmaf(v, scale[c], shift[c]), 0.f);
                C[(size_t)r * ldc + c] = v;
            }
        }
    }
}

// aggregation for 185-channel hidden layers + bias + bn + relu, writes into XS
__global__ void k_aggregate_h(const float* __restrict__ tmp,
                              const float* __restrict__ bias,
                              const float* __restrict__ scale,
                              const float* __restrict__ shift,
                              int colofs, int N) {
    int n = blockIdx.x;
    int c = threadIdx.x;
    if (n >= N || c >= HID) return;
    int s0 = g_offs[n], s1 = g_offs[n + 1];
    float acc = 0.f;
    int e = s0;
    for (; e + 4 <= s1; e += 4) {
        int i0 = g_csr_src[e],   i1 = g_csr_src[e+1];
        int i2 = g_csr_src[e+2], i3 = g_csr_src[e+3];
        float w0 = g_csr_w[e],   w1 = g_csr_w[e+1];
        float w2 = g_csr_w[e+2], w3 = g_csr_w[e+3];
        acc += w0 * tmp[i0 * HID + c];
        acc += w1 * tmp[i1 * HID + c];
        acc += w2 * tmp[i2 * HID + c];
        acc += w3 * tmp[i3 * HID + c];
    }
    for (; e < s1; ++e) acc += g_csr_w[e] * tmp[g_csr_src[e] * HID + c];
    float dn = g_dis[n];
    float v = dn * acc + dn * dn * tmp[n * HID + c] + bias[c];
    v = fmaxf(fmaf(v, scale[c], shift[c]), 0.f);
    g_xs[n * JKDIM + colofs + c] = v;
}

__global__ void k_pool(const int* __restrict__ batch, int N) {
    int idx = blockIdx.x * blockDim.x + threadIdx.x;
    if (idx >= N * HID) return;
    int n = idx / HID, c = idx - n * HID;
    unsigned u = enc_f(g_hjk[idx]);
    atomicMax(&g_pool[batch[n] * HID + c], u);
}

__global__ void k_finalize(const float* __restrict__ Wout,
                           const float* __restrict__ bout,
                           float* __restrict__ out, int G) {
    int g = blockIdx.x;
    int t = threadIdx.x;
    __shared__ float red[256];
    float p = 0.f;
    for (int c = t; c < HID; c += 256)
        p += dec_f(g_pool[g * HID + c]) * Wout[c];
    red[t] = p;
    __syncthreads();
    for (int o = 128; o; o >>= 1) {
        if (t < o) red[t] += red[t + o];
        __syncthreads();
    }
    if (t == 0) out[g] = red[0] + bout[0];
}

// ---------------- host launcher ----------------
extern "C" void kernel_launch(void* const* d_in, const int* in_sizes, int n_in,
                              void* d_out, int out_size) {
    const float* x       = (const float*)d_in[0];
    const int*   ei      = (const int*)  d_in[1];
    const int*   batch   = (const int*)  d_in[2];
    const float* W0      = (const float*)d_in[3];
    const float* b0      = (const float*)d_in[4];
    const float* W_h     = (const float*)d_in[5];
    const float* b_h     = (const float*)d_in[6];
    const float* bn_g    = (const float*)d_in[7];
    const float* bn_b    = (const float*)d_in[8];
    const float* bn_m    = (const float*)d_in[9];
    const float* bn_v    = (const float*)d_in[10];
    const float* W_jk    = (const float*)d_in[11];
    const float* b_jk    = (const float*)d_in[12];
    const float* W_out   = (const float*)d_in[13];
    const float* b_out   = (const float*)d_in[14];
    float* out = (float*)d_out;

    int N = in_sizes[0] / INCH;
    int E = in_sizes[1] / 2;
    int G = out_size;

    float* xs0; cudaGetSymbolAddress((void**)&xs0, g_xs);
    float* tmp; cudaGetSymbolAddress((void**)&tmp, g_tmp);
    float* ax;  cudaGetSymbolAddress((void**)&ax,  g_ax);
    float* hjk; cudaGetSymbolAddress((void**)&hjk, g_hjk);
    float* bns; cudaGetSymbolAddress((void**)&bns, g_bnscale);
    float* bnh; cudaGetSymbolAddress((void**)&bnh, g_bnshift);

    int initN = (N > G * HID) ? N : G * HID;
    k_init<<<(initN + 255) / 256, 256>>>(N, G);
    k_count<<<(E + 255) / 256, 256>>>(ei, E);
    k_rsqrt_deg<<<(N + 255) / 256, 256>>>(N);
    k_scan<<<1, 1024>>>(N);
    k_cursor<<<(N + 255) / 256, 256>>>(N);
    k_fill<<<(E + 255) / 256, 256>>>(ei, E);
    k_aggregate_x<<<(N * 32 + 255) / 256, 256>>>(x, N);
    k_bn_pre<<<(4 * HID + 255) / 256, 256>>>(bn_g, bn_b, bn_m, bn_v);

    dim3 grid(3, (N + 127) / 128);   // 3 col tiles of 64 cover 185

    // layer 0: (A^ x) @ W0 + b0, bn0, relu -> XS[:,0:185]
    k_mma<<<grid, 256>>>(ax, INCH, W0, HID, xs0, JKDIM,
                         N, INCH, HID, b0, bns, bnh, 2);

    // layers 1..3
    for (int i = 1; i <= 3; i++) {
        k_mma<<<grid, 256>>>(xs0 + (i - 1) * HID, JKDIM,
                             W_h + (i - 1) * HID * HID, HID,
                             tmp, HID, N, HID, HID,
                             (const float*)0, (const float*)0, (const float*)0, 0);
        k_aggregate_h<<<N, 192>>>(tmp, b_h + (i - 1) * HID,
                                  bns + i * HID, bnh + i * HID, i * HID, N);
    }

    // JK: XS[N,740] @ W_jk + b_jk -> hjk[N,185]
    k_mma<<<grid, 256>>>(xs0, JKDIM, W_jk, HID, hjk, HID,
                         N, JKDIM, HID, b_jk, (const float*)0, (const float*)0, 1);

    k_pool<<<(N * HID + 255) / 256, 256>>>(batch, N);
    k_finalize<<<G, 256>>>(W_out, b_out, out, G);
}

// round 4
// speedup vs baseline: 2.0477x; 2.0477x over previous
#include <cuda_runtime.h>
#include <cuda_bf16.h>
#include <cstdint>
#include <math.h>

#define NMAX   25000
#define EMAX   400000
#define GMAX   1000
#define HID    185
#define INCH   9
#define LDAH   768      // padded concat width (4*192)

// ---------------- scratch ----------------
__device__ int      g_cnt[NMAX];
__device__ int      g_part[NMAX];
__device__ int      g_bsum[128];
__device__ int      g_bpre[128];
__device__ int      g_offs[NMAX + 1];
__device__ int      g_cursor[NMAX];
__device__ float    g_dis[NMAX];
__device__ int      g_csr_src[EMAX];
__device__ float    g_csr_w[EMAX];
__device__ __align__(16) __nv_bfloat16 g_A0h[NMAX * 64];
__device__ __align__(16) __nv_bfloat16 g_A0l[NMAX * 64];
__device__ __align__(16) __nv_bfloat16 g_Ah[NMAX * LDAH];
__device__ __align__(16) __nv_bfloat16 g_Al[NMAX * LDAH];
// transposed/split/padded weights: W0t [192][64], Wht 3x[192][192], Wjkt [192][768]
__device__ __align__(16) __nv_bfloat16 g_W0th[192 * 64];
__device__ __align__(16) __nv_bfloat16 g_W0tl[192 * 64];
__device__ __align__(16) __nv_bfloat16 g_Whth[3 * 192 * 192];
__device__ __align__(16) __nv_bfloat16 g_Whtl[3 * 192 * 192];
__device__ __align__(16) __nv_bfloat16 g_Wjkth[192 * 768];
__device__ __align__(16) __nv_bfloat16 g_Wjktl[192 * 768];
__device__ float    g_tmp[NMAX * HID];
__device__ unsigned g_pool[GMAX * HID];
__device__ float    g_bnscale[4 * HID];
__device__ float    g_bnshift[4 * HID];

// ---------------- helpers ----------------
__device__ __forceinline__ unsigned enc_f(float f) {
    unsigned u = __float_as_uint(f);
    return (u & 0x80000000u) ? ~u : (u | 0x80000000u);
}
__device__ __forceinline__ float dec_f(unsigned e) {
    return (e & 0x80000000u) ? __uint_as_float(e & 0x7FFFFFFFu) : __uint_as_float(~e);
}
__device__ __forceinline__ void split_bf(float v, __nv_bfloat16& h, __nv_bfloat16& l) {
    h = __float2bfloat16(v);
    l = __float2bfloat16(v - __bfloat162float(h));
}
__device__ __forceinline__ uint32_t smem_u32(const void* p) {
    uint32_t a;
    asm("{ .reg .u64 t; cvta.to.shared.u64 t, %1; cvt.u32.u64 %0, t; }" : "=r"(a) : "l"(p));
    return a;
}
#define LDSM4(r0, r1, r2, r3, addr) \
    asm volatile("ldmatrix.sync.aligned.m8n8.x4.shared.b16 {%0,%1,%2,%3}, [%4];" \
        : "=r"(r0), "=r"(r1), "=r"(r2), "=r"(r3) : "r"(addr))
__device__ __forceinline__ void mma16(float* c, const uint32_t* a, const uint32_t* b) {
    asm volatile("mma.sync.aligned.m16n8k16.row.col.f32.bf16.bf16.f32 "
        "{%0,%1,%2,%3}, {%4,%5,%6,%7}, {%8,%9}, {%0,%1,%2,%3};"
        : "+f"(c[0]), "+f"(c[1]), "+f"(c[2]), "+f"(c[3])
        : "r"(a[0]), "r"(a[1]), "r"(a[2]), "r"(a[3]), "r"(b[0]), "r"(b[1]));
}

// ---------------- graph preprocessing ----------------
__global__ void k_init(int N, int G) {
    int i = blockIdx.x * blockDim.x + threadIdx.x;
    if (i < N) g_cnt[i] = 0;
    if (i < G * HID) g_pool[i] = 0x007FFFFFu;   // enc(-inf)
}
__global__ void k_count(const int* __restrict__ ei, int E) {
    int e = blockIdx.x * blockDim.x + threadIdx.x;
    if (e < E) atomicAdd(&g_cnt[ei[E + e]], 1);
}
__global__ void k_scan_blk(int N) {
    __shared__ int sh[256];
    int i = blockIdx.x * 256 + threadIdx.x;
    int v = (i < N) ? g_cnt[i] : 0;
    sh[threadIdx.x] = v;
    __syncthreads();
    for (int o = 1; o < 256; o <<= 1) {
        int a = (threadIdx.x >= o) ? sh[threadIdx.x - o] : 0;
        __syncthreads();
        sh[threadIdx.x] += a;
        __syncthreads();
    }
    if (i < N) g_part[i] = sh[threadIdx.x] - v;
    if (threadIdx.x == 255) g_bsum[blockIdx.x] = sh[255];
}
__global__ void k_scan_top(int SB) {
    __shared__ int sh[128];
    int t = threadIdx.x;
    int v = (t < SB) ? g_bsum[t] : 0;
    sh[t] = v;
    __syncthreads();
    for (int o = 1; o < 128; o <<= 1) {
        int a = (t >= o) ? sh[t - o] : 0;
        __syncthreads();
        sh[t] += a;
        __syncthreads();
    }
    g_bpre[t] = sh[t] - v;
}
__global__ void k_scan_add(int N) {
    int i = blockIdx.x * 256 + threadIdx.x;
    if (i >= N) return;
    int off = g_part[i] + g_bpre[blockIdx.x];
    int c = g_cnt[i];
    g_offs[i] = off;
    g_cursor[i] = off;
    if (i == N - 1) g_offs[N] = off + c;
    g_dis[i] = rsqrtf((float)c + 1.0f);   // +1 self-loop
}
__global__ void k_fill(const int* __restrict__ ei, int E) {
    int e = blockIdx.x * blockDim.x + threadIdx.x;
    if (e >= E) return;
    int s = ei[e], d = ei[E + e];
    int p = atomicAdd(&g_cursor[d], 1);
    g_csr_src[p] = s;
    g_csr_w[p]   = g_dis[s];
}

// aggregate raw x (9 ch) -> split bf16 A0 [N x 64]
__global__ void k_aggregate_x(const float* __restrict__ x, int N) {
    int warp = (blockIdx.x * blockDim.x + threadIdx.x) >> 5;
    int lane = threadIdx.x & 31;
    if (warp >= N) return;
    int n = warp;
    int s0 = g_offs[n], s1 = g_offs[n + 1];
    float acc[INCH];
#pragma unroll
    for (int c = 0; c < INCH; c++) acc[c] = 0.f;
    for (int e = s0 + lane; e < s1; e += 32) {
        int s = g_csr_src[e];
        float w = g_csr_w[e];
#pragma unroll
        for (int c = 0; c < INCH; c++) acc[c] += w * x[s * INCH + c];
    }
#pragma unroll
    for (int c = 0; c < INCH; c++)
#pragma unroll
        for (int o = 16; o; o >>= 1)
            acc[c] += __shfl_xor_sync(0xffffffffu, acc[c], o);
    if (lane == 0) {
        float dn = g_dis[n];
#pragma unroll
        for (int c = 0; c < INCH; c++) {
            float v = dn * acc[c] + dn * dn * x[n * INCH + c];
            __nv_bfloat16 h, l; split_bf(v, h, l);
            g_A0h[n * 64 + c] = h;
            g_A0l[n * 64 + c] = l;
        }
    }
    for (int c = INCH + lane; c < 64; c += 32) {
        g_A0h[n * 64 + c] = __float2bfloat16(0.f);
        g_A0l[n * 64 + c] = __float2bfloat16(0.f);
    }
}

// weight transpose + split + pad, and BN fold. blocks: [0,48) W0 | [48,480) Wh | [480,1056) Wjk | [1056,1059) bn
__global__ void k_wprep(const float* __restrict__ W0, const float* __restrict__ Wh,
                        const float* __restrict__ Wjk,
                        const float* __restrict__ gamma, const float* __restrict__ beta,
                        const float* __restrict__ mean, const float* __restrict__ var) {
    int b = blockIdx.x, t = threadIdx.x;
    if (b < 48) {
        int idx = b * 256 + t;
        int n = idx >> 6, k = idx & 63;
        float v = (n < HID && k < INCH) ? W0[k * HID + n] : 0.f;
        __nv_bfloat16 h, l; split_bf(v, h, l);
        g_W0th[idx] = h; g_W0tl[idx] = l;
    } else if (b < 480) {
        int q = b - 48;
        int L = q / 144;
        int idx = (q - L * 144) * 256 + t;        // 0..36863
        int n = idx / 192, k = idx % 192;
        float v = (n < HID && k < HID) ? Wh[(size_t)L * HID * HID + k * HID + n] : 0.f;
        __nv_bfloat16 h, l; split_bf(v, h, l);
        g_Whth[L * 36864 + idx] = h; g_Whtl[L * 36864 + idx] = l;
    } else if (b < 1056) {
        int idx = (b - 480) * 256 + t;            // 0..147455
        int n = idx / 768, k = idx % 768;
        int layer = k / 192, c = k % 192;
        float v = (n < HID && c < HID) ? Wjk[(size_t)(layer * HID + c) * HID + n] : 0.f;
        __nv_bfloat16 h, l; split_bf(v, h, l);
        g_Wjkth[idx] = h; g_Wjktl[idx] = l;
    } else {
        int i = (b - 1056) * 256 + t;
        if (i < 4 * HID) {
            float sc = gamma[i] * rsqrtf(var[i] + 1e-5f);
            g_bnscale[i] = sc;
            g_bnshift[i] = beta[i] - mean[i] * sc;
        }
    }
}

// ---------------- bf16x3 tensor-core GEMM (m16n8k16 + ldmatrix) ----------------
// C[Nrows, 185] = A[Nrows, 64*Ktiles] @ B^T   (B stored [192 n][ldb k], pre-split)
// CTA 128x64, 8 warps (4x2) of 32x32, BK=64.
// mode 0: fp32 -> Cf[r*185+c]
// mode 2: bias+bn+relu -> split bf16 into Oh/Ol at col c (c>=185 -> 0)
// mode 3: bias -> atomicMax pool[batch[r]*185+c]
// smem (bf16 units): sAh 0, sAl 9216, sBh 18432, sBl 23040; total 27648 (55296 B)
#define SMEM_BYTES 55296
__global__ void __launch_bounds__(256)
k_mma(const __nv_bfloat16* __restrict__ Ah, const __nv_bfloat16* __restrict__ Al, int lda,
      const __nv_bfloat16* __restrict__ Bh, const __nv_bfloat16* __restrict__ Bl, int ldb,
      int Nrows, int Ktiles,
      float* __restrict__ Cf,
      __nv_bfloat16* __restrict__ Oh, __nv_bfloat16* __restrict__ Ol,
      const float* __restrict__ bias, const float* __restrict__ scale,
      const float* __restrict__ shift,
      const int* __restrict__ batch, unsigned* __restrict__ pool, int mode) {
    extern __shared__ __align__(16) __nv_bfloat16 sm[];
    __nv_bfloat16* sAh = sm;
    __nv_bfloat16* sAl = sm + 9216;
    __nv_bfloat16* sBh = sm + 18432;
    __nv_bfloat16* sBl = sm + 23040;

    int tid = threadIdx.x, lane = tid & 31, w = tid >> 5;
    int wm = w & 3, wn = w >> 2;
    int rowBase = blockIdx.y * 128, colBase = blockIdx.x * 64;

    float acc[2][4][4];
#pragma unroll
    for (int i = 0; i < 2; i++)
#pragma unroll
        for (int j = 0; j < 4; j++)
#pragma unroll
            for (int q = 0; q < 4; q++) acc[i][j][q] = 0.f;

    // ldmatrix lane addresses (bytes)
    uint32_t aA = smem_u32(sAh) +
        ((uint32_t)((wm * 32 + (lane & 15)) * 72 + (lane >> 4) * 8) << 1);
    uint32_t aB = smem_u32(sBh) +
        ((uint32_t)((wn * 32 + (lane & 7) + ((lane >> 4) << 3)) * 72 + ((lane >> 3) & 1) * 8) << 1);
    const uint32_t A_LO = 18432;   // bytes: sAl - sAh
    const uint32_t B_LO = 9216;    // bytes: sBl - sBh
    const uint32_t MF   = 2304;    // 16 rows * 144 B

    for (int kt = 0; kt < Ktiles; kt++) {
        int k0 = kt * 64;
        // A tiles (hi/lo): 128x64, uint4 vectorized
#pragma unroll
        for (int s = 0; s < 4; s++) {
            int idx = tid + s * 256;
            int r = idx >> 3, j = idx & 7;
            int gr = rowBase + r;
            uint4 vh = make_uint4(0, 0, 0, 0), vl = vh;
            if (gr < Nrows) {
                size_t go = ((size_t)gr * lda + k0 + j * 8) >> 3;
                vh = ((const uint4*)Ah)[go];
                vl = ((const uint4*)Al)[go];
            }
            int so = r * 9 + j;
            ((uint4*)sAh)[so] = vh;
            ((uint4*)sAl)[so] = vl;
        }
        // B tiles (hi/lo): 64x64
#pragma unroll
        for (int s = 0; s < 2; s++) {
            int idx = tid + s * 256;
            int n = idx >> 3, j = idx & 7;
            size_t go = ((size_t)(colBase + n) * ldb + k0 + j * 8) >> 3;
            uint4 vh = ((const uint4*)Bh)[go];
            uint4 vl = ((const uint4*)Bl)[go];
            int so = n * 9 + j;
            ((uint4*)sBh)[so] = vh;
            ((uint4*)sBl)[so] = vl;
        }
        __syncthreads();

#pragma unroll
        for (int ks = 0; ks < 4; ks++) {
            uint32_t kso = ks * 32;
            uint32_t bh[4][2], bl[4][2];
            LDSM4(bh[0][0], bh[0][1], bh[1][0], bh[1][1], aB + kso);
            LDSM4(bh[2][0], bh[2][1], bh[3][0], bh[3][1], aB + MF + kso);
            LDSM4(bl[0][0], bl[0][1], bl[1][0], bl[1][1], aB + B_LO + kso);
            LDSM4(bl[2][0], bl[2][1], bl[3][0], bl[3][1], aB + B_LO + MF + kso);
#pragma unroll
            for (int mf = 0; mf < 2; mf++) {
                uint32_t ah[4], al[4];
                LDSM4(ah[0], ah[1], ah[2], ah[3], aA + mf * MF + kso);
                LDSM4(al[0], al[1], al[2], al[3], aA + A_LO + mf * MF + kso);
#pragma unroll
                for (int nf = 0; nf < 4; nf++) {
                    mma16(acc[mf][nf], ah, bh[nf]);
                    mma16(acc[mf][nf], ah, bl[nf]);
                    mma16(acc[mf][nf], al, bh[nf]);
                }
            }
        }
        __syncthreads();
    }

    // epilogue
    int gid = lane >> 2, tig = lane & 3;
#pragma unroll
    for (int mf = 0; mf < 2; mf++) {
#pragma unroll
        for (int q = 0; q < 4; q++) {
            int r = rowBase + wm * 32 + mf * 16 + gid + ((q & 2) ? 8 : 0);
            if (r >= Nrows) continue;
            int bidx = (mode == 3) ? batch[r] : 0;
#pragma unroll
            for (int nf = 0; nf < 4; nf++) {
                int c = colBase + wn * 32 + nf * 8 + tig * 2 + (q & 1);
                float v = acc[mf][nf][q];
                if (mode == 0) {
                    if (c < HID) Cf[(size_t)r * HID + c] = v;
                } else if (mode == 2) {
                    float o = 0.f;
                    if (c < HID)
                        o = fmaxf(fmaf(v + bias[c], scale[c], shift[c]), 0.f);
                    __nv_bfloat16 h, l; split_bf(o, h, l);
                    size_t di = (size_t)r * LDAH + c;
                    Oh[di] = h; Ol[di] = l;
                } else {
                    if (c < HID)
                        atomicMax(&pool[bidx * HID + c], enc_f(v + bias[c]));
                }
            }
        }
    }
}

// aggregation for hidden layers: gather g_tmp rows, bias+bn+relu, split write into concat buffer
__global__ void k_aggregate_h(const float* __restrict__ tmp,
                              const float* __restrict__ bias,
                              const float* __restrict__ scale,
                              const float* __restrict__ shift,
                              int colofs, int N) {
    int n = blockIdx.x;
    int c = threadIdx.x;   // 0..191
    float v = 0.f;
    if (c < HID) {
        int s0 = g_offs[n], s1 = g_offs[n + 1];
        float acc = 0.f;
        int e = s0;
        for (; e + 4 <= s1; e += 4) {
            int i0 = g_csr_src[e],   i1 = g_csr_src[e + 1];
            int i2 = g_csr_src[e + 2], i3 = g_csr_src[e + 3];
            float w0 = g_csr_w[e],   w1 = g_csr_w[e + 1];
            float w2 = g_csr_w[e + 2], w3 = g_csr_w[e + 3];
            acc += w0 * tmp[(size_t)i0 * HID + c];
            acc += w1 * tmp[(size_t)i1 * HID + c];
            acc += w2 * tmp[(size_t)i2 * HID + c];
            acc += w3 * tmp[(size_t)i3 * HID + c];
        }
        for (; e < s1; ++e) acc += g_csr_w[e] * tmp[(size_t)g_csr_src[e] * HID + c];
        float dn = g_dis[n];
        v = dn * acc + dn * dn * tmp[(size_t)n * HID + c] + bias[c];
        v = fmaxf(fmaf(v, scale[c], shift[c]), 0.f);
    }
    __nv_bfloat16 h, l; split_bf(v, h, l);
    size_t di = (size_t)n * LDAH + colofs + c;
    g_Ah[di] = h;
    g_Al[di] = l;
}

__global__ void k_finalize(const float* __restrict__ Wout,
                           const float* __restrict__ bout,
                           float* __restrict__ out, int G) {
    int g = blockIdx.x, t = threadIdx.x;
    __shared__ float red[256];
    float p = 0.f;
    for (int c = t; c < HID; c += 256)
        p += dec_f(g_pool[g * HID + c]) * Wout[c];
    red[t] = p;
    __syncthreads();
    for (int o = 128; o; o >>= 1) {
        if (t < o) red[t] += red[t + o];
        __syncthreads();
    }
    if (t == 0) out[g] = red[0] + bout[0];
}

// ---------------- host launcher ----------------
extern "C" void kernel_launch(void* const* d_in, const int* in_sizes, int n_in,
                              void* d_out, int out_size) {
    const float* x     = (const float*)d_in[0];
    const int*   ei    = (const int*)  d_in[1];
    const int*   batch = (const int*)  d_in[2];
    const float* W0    = (const float*)d_in[3];
    const float* b0    = (const float*)d_in[4];
    const float* W_h   = (const float*)d_in[5];
    const float* b_h   = (const float*)d_in[6];
    const float* bn_g  = (const float*)d_in[7];
    const float* bn_b  = (const float*)d_in[8];
    const float* bn_m  = (const float*)d_in[9];
    const float* bn_v  = (const float*)d_in[10];
    const float* W_jk  = (const float*)d_in[11];
    const float* b_jk  = (const float*)d_in[12];
    const float* W_out = (const float*)d_in[13];
    const float* b_out = (const float*)d_in[14];
    float* out = (float*)d_out;

    int N = in_sizes[0] / INCH;
    int E = in_sizes[1] / 2;
    int G = out_size;
    int SB = (N + 255) / 256;

    cudaFuncSetAttribute(k_mma, cudaFuncAttributeMaxDynamicSharedMemorySize, SMEM_BYTES);

    __nv_bfloat16 *a0h, *a0l, *ah, *al, *w0h, *w0l, *whh, *whl, *wjh, *wjl;
    cudaGetSymbolAddress((void**)&a0h, g_A0h);
    cudaGetSymbolAddress((void**)&a0l, g_A0l);
    cudaGetSymbolAddress((void**)&ah,  g_Ah);
    cudaGetSymbolAddress((void**)&al,  g_Al);
    cudaGetSymbolAddress((void**)&w0h, g_W0th);
    cudaGetSymbolAddress((void**)&w0l, g_W0tl);
    cudaGetSymbolAddress((void**)&whh, g_Whth);
    cudaGetSymbolAddress((void**)&whl, g_Whtl);
    cudaGetSymbolAddress((void**)&wjh, g_Wjkth);
    cudaGetSymbolAddress((void**)&wjl, g_Wjktl);
    float *tmp, *bns, *bnh;
    cudaGetSymbolAddress((void**)&tmp, g_tmp);
    cudaGetSymbolAddress((void**)&bns, g_bnscale);
    cudaGetSymbolAddress((void**)&bnh, g_bnshift);
    unsigned* pool;
    cudaGetSymbolAddress((void**)&pool, g_pool);

    int initN = (N > G * HID) ? N : G * HID;
    k_init<<<(initN + 255) / 256, 256>>>(N, G);
    k_count<<<(E + 255) / 256, 256>>>(ei, E);
    k_scan_blk<<<SB, 256>>>(N);
    k_scan_top<<<1, 128>>>(SB);
    k_scan_add<<<SB, 256>>>(N);
    k_fill<<<(E + 255) / 256, 256>>>(ei, E);
    k_aggregate_x<<<(N * 32 + 255) / 256, 256>>>(x, N);
    k_wprep<<<1059, 256>>>(W0, W_h, W_jk, bn_g, bn_b, bn_m, bn_v);

    dim3 grid(3, (N + 127) / 128);

    // layer 0: (Âx)@W0 -> bias+bn0+relu -> split into concat cols [0,192)
    k_mma<<<grid, 256, SMEM_BYTES>>>(a0h, a0l, 64, w0h, w0l, 64, N, 1,
                                     (float*)0, ah, al,
                                     b0, bns, bnh, (const int*)0, (unsigned*)0, 2);
    // hidden layers 1..3
    for (int i = 1; i <= 3; i++) {
        k_mma<<<grid, 256, SMEM_BYTES>>>(ah + (size_t)(i - 1) * 192,
                                         al + (size_t)(i - 1) * 192, LDAH,
                                         whh + (size_t)(i - 1) * 36864,
                                         whl + (size_t)(i - 1) * 36864, 192,
                                         N, 3, tmp,
                                         (__nv_bfloat16*)0, (__nv_bfloat16*)0,
                                         (const float*)0, (const float*)0, (const float*)0,
                                         (const int*)0, (unsigned*)0, 0);
        k_aggregate_h<<<N, 192>>>(tmp, b_h + (size_t)(i - 1) * HID,
                                  bns + i * HID, bnh + i * HID, i * 192, N);
    }
    // JK GEMM fused with max-pool: [N,768]@Wjk^T + b_jk -> atomicMax pool
    k_mma<<<grid, 256, SMEM_BYTES>>>(ah, al, LDAH, wjh, wjl, 768, N, 12,
                                     (float*)0, (__nv_bfloat16*)0, (__nv_bfloat16*)0,
                                     b_jk, (const float*)0, (const float*)0,
                                     batch, pool, 3);

    k_finalize<<<G, 256>>>(W_out, b_out, out, G);
}

// round 5
// speedup vs baseline: 2.6918x; 1.3145x over previous
#include <cuda_runtime.h>
#include <cuda_bf16.h>
#include <cstdint>
#include <math.h>

#define NMAX   25000
#define EMAX   400000
#define GMAX   1000
#define HID    185
#define INCH   9
#define LDAH   768      // padded concat width (4*192)
#define LDT    186      // tmp row stride (even -> float2-aligned)

// ---------------- scratch ----------------
__device__ int      g_cnt[NMAX];
__device__ int      g_part[NMAX];
__device__ int      g_bsum[128];
__device__ int      g_bpre[128];
__device__ int      g_offs[NMAX + 1];
__device__ int      g_cursor[NMAX];
__device__ float    g_dis[NMAX];
__device__ int      g_csr_src[EMAX];
__device__ float    g_csr_w[EMAX];
__device__ __align__(16) __nv_bfloat16 g_A0h[NMAX * 64];
__device__ __align__(16) __nv_bfloat16 g_A0l[NMAX * 64];
__device__ __align__(16) __nv_bfloat16 g_Ah[NMAX * LDAH];
__device__ __align__(16) __nv_bfloat16 g_Al[NMAX * LDAH];
__device__ __align__(16) __nv_bfloat16 g_W0th[192 * 64];
__device__ __align__(16) __nv_bfloat16 g_W0tl[192 * 64];
__device__ __align__(16) __nv_bfloat16 g_Whth[3 * 192 * 192];
__device__ __align__(16) __nv_bfloat16 g_Whtl[3 * 192 * 192];
__device__ __align__(16) __nv_bfloat16 g_Wjkth[192 * 768];
__device__ __align__(16) __nv_bfloat16 g_Wjktl[192 * 768];
__device__ __align__(16) float g_tmp[NMAX * LDT];
__device__ unsigned g_pool[GMAX * HID];
__device__ float    g_bnscale[4 * HID];
__device__ float    g_bnshift[4 * HID];

// ---------------- helpers ----------------
__device__ __forceinline__ unsigned enc_f(float f) {
    unsigned u = __float_as_uint(f);
    return (u & 0x80000000u) ? ~u : (u | 0x80000000u);
}
__device__ __forceinline__ float dec_f(unsigned e) {
    return (e & 0x80000000u) ? __uint_as_float(e & 0x7FFFFFFFu) : __uint_as_float(~e);
}
__device__ __forceinline__ void split_bf(float v, __nv_bfloat16& h, __nv_bfloat16& l) {
    h = __float2bfloat16(v);
    l = __float2bfloat16(v - __bfloat162float(h));
}
__device__ __forceinline__ uint32_t smem_u32(const void* p) {
    uint32_t a;
    asm("{ .reg .u64 t; cvta.to.shared.u64 t, %1; cvt.u32.u64 %0, t; }" : "=r"(a) : "l"(p));
    return a;
}
#define LDSM4(r0, r1, r2, r3, addr) \
    asm volatile("ldmatrix.sync.aligned.m8n8.x4.shared.b16 {%0,%1,%2,%3}, [%4];" \
        : "=r"(r0), "=r"(r1), "=r"(r2), "=r"(r3) : "r"(addr))
__device__ __forceinline__ void mma16(float* c, const uint32_t* a, const uint32_t* b) {
    asm volatile("mma.sync.aligned.m16n8k16.row.col.f32.bf16.bf16.f32 "
        "{%0,%1,%2,%3}, {%4,%5,%6,%7}, {%8,%9}, {%0,%1,%2,%3};"
        : "+f"(c[0]), "+f"(c[1]), "+f"(c[2]), "+f"(c[3])
        : "r"(a[0]), "r"(a[1]), "r"(a[2]), "r"(a[3]), "r"(b[0]), "r"(b[1]));
}
#define CP16(dst, src, sz) \
    asm volatile("cp.async.cg.shared.global [%0], [%1], 16, %2;" \
        :: "r"(dst), "l"(src), "r"(sz) : "memory")
#define CP_COMMIT() asm volatile("cp.async.commit_group;" ::: "memory")
#define CP_WAIT0()  asm volatile("cp.async.wait_group 0;" ::: "memory")
#define CP_WAIT1()  asm volatile("cp.async.wait_group 1;" ::: "memory")

// ---------------- graph preprocessing ----------------
__global__ void k_init(int N, int G) {
    int i = blockIdx.x * blockDim.x + threadIdx.x;
    if (i < N) g_cnt[i] = 0;
    if (i < G * HID) g_pool[i] = 0x007FFFFFu;   // enc(-inf)
}
__global__ void k_count(const int* __restrict__ ei, int E) {
    int e = blockIdx.x * blockDim.x + threadIdx.x;
    if (e < E) atomicAdd(&g_cnt[ei[E + e]], 1);
}
__global__ void k_scan_blk(int N) {
    __shared__ int sh[256];
    int i = blockIdx.x * 256 + threadIdx.x;
    int v = (i < N) ? g_cnt[i] : 0;
    sh[threadIdx.x] = v;
    __syncthreads();
    for (int o = 1; o < 256; o <<= 1) {
        int a = (threadIdx.x >= o) ? sh[threadIdx.x - o] : 0;
        __syncthreads();
        sh[threadIdx.x] += a;
        __syncthreads();
    }
    if (i < N) g_part[i] = sh[threadIdx.x] - v;
    if (threadIdx.x == 255) g_bsum[blockIdx.x] = sh[255];
}
__global__ void k_scan_top(int SB) {
    __shared__ int sh[128];
    int t = threadIdx.x;
    int v = (t < SB) ? g_bsum[t] : 0;
    sh[t] = v;
    __syncthreads();
    for (int o = 1; o < 128; o <<= 1) {
        int a = (t >= o) ? sh[t - o] : 0;
        __syncthreads();
        sh[t] += a;
        __syncthreads();
    }
    g_bpre[t] = sh[t] - v;
}
__global__ void k_scan_add(int N) {
    int i = blockIdx.x * 256 + threadIdx.x;
    if (i >= N) return;
    int off = g_part[i] + g_bpre[blockIdx.x];
    int c = g_cnt[i];
    g_offs[i] = off;
    g_cursor[i] = off;
    if (i == N - 1) g_offs[N] = off + c;
    g_dis[i] = rsqrtf((float)c + 1.0f);   // +1 self-loop
}
__global__ void k_fill(const int* __restrict__ ei, int E) {
    int e = blockIdx.x * blockDim.x + threadIdx.x;
    if (e >= E) return;
    int s = ei[e], d = ei[E + e];
    int p = atomicAdd(&g_cursor[d], 1);
    g_csr_src[p] = s;
    g_csr_w[p]   = g_dis[s];
}

// aggregate raw x (9 ch) -> split bf16 A0 [N x 64]
__global__ void k_aggregate_x(const float* __restrict__ x, int N) {
    int warp = (blockIdx.x * blockDim.x + threadIdx.x) >> 5;
    int lane = threadIdx.x & 31;
    if (warp >= N) return;
    int n = warp;
    int s0 = g_offs[n], s1 = g_offs[n + 1];
    float acc[INCH];
#pragma unroll
    for (int c = 0; c < INCH; c++) acc[c] = 0.f;
    for (int e = s0 + lane; e < s1; e += 32) {
        int s = g_csr_src[e];
        float w = g_csr_w[e];
#pragma unroll
        for (int c = 0; c < INCH; c++) acc[c] += w * x[s * INCH + c];
    }
#pragma unroll
    for (int c = 0; c < INCH; c++)
#pragma unroll
        for (int o = 16; o; o >>= 1)
            acc[c] += __shfl_xor_sync(0xffffffffu, acc[c], o);
    if (lane == 0) {
        float dn = g_dis[n];
#pragma unroll
        for (int c = 0; c < INCH; c++) {
            float v = dn * acc[c] + dn * dn * x[n * INCH + c];
            __nv_bfloat16 h, l; split_bf(v, h, l);
            g_A0h[n * 64 + c] = h;
            g_A0l[n * 64 + c] = l;
        }
    }
    for (int c = INCH + lane; c < 64; c += 32) {
        g_A0h[n * 64 + c] = __float2bfloat16(0.f);
        g_A0l[n * 64 + c] = __float2bfloat16(0.f);
    }
}

// weight transpose + split + pad, and BN fold
__global__ void k_wprep(const float* __restrict__ W0, const float* __restrict__ Wh,
                        const float* __restrict__ Wjk,
                        const float* __restrict__ gamma, const float* __restrict__ beta,
                        const float* __restrict__ mean, const float* __restrict__ var) {
    int b = blockIdx.x, t = threadIdx.x;
    if (b < 48) {
        int idx = b * 256 + t;
        int n = idx >> 6, k = idx & 63;
        float v = (n < HID && k < INCH) ? W0[k * HID + n] : 0.f;
        __nv_bfloat16 h, l; split_bf(v, h, l);
        g_W0th[idx] = h; g_W0tl[idx] = l;
    } else if (b < 480) {
        int q = b - 48;
        int L = q / 144;
        int idx = (q - L * 144) * 256 + t;
        int n = idx / 192, k = idx % 192;
        float v = (n < HID && k < HID) ? Wh[(size_t)L * HID * HID + k * HID + n] : 0.f;
        __nv_bfloat16 h, l; split_bf(v, h, l);
        g_Whth[L * 36864 + idx] = h; g_Whtl[L * 36864 + idx] = l;
    } else if (b < 1056) {
        int idx = (b - 480) * 256 + t;
        int n = idx / 768, k = idx % 768;
        int layer = k / 192, c = k % 192;
        float v = (n < HID && c < HID) ? Wjk[(size_t)(layer * HID + c) * HID + n] : 0.f;
        __nv_bfloat16 h, l; split_bf(v, h, l);
        g_Wjkth[idx] = h; g_Wjktl[idx] = l;
    } else {
        int i = (b - 1056) * 256 + t;
        if (i < 4 * HID) {
            float sc = gamma[i] * rsqrtf(var[i] + 1e-5f);
            g_bnscale[i] = sc;
            g_bnshift[i] = beta[i] - mean[i] * sc;
        }
    }
}

// ---------------- bf16x3 GEMM, cp.async double-buffered ----------------
// stage layout (bytes): sAh 0, sAl 18432, sBh 36864, sBl 46080; stage size 55296
#define STG 55296
#define SMEM_BYTES (2 * STG)

__device__ __forceinline__ void ld_stage(
    uint32_t smb,
    const __nv_bfloat16* __restrict__ Ah, const __nv_bfloat16* __restrict__ Al, int lda,
    const __nv_bfloat16* __restrict__ Bh, const __nv_bfloat16* __restrict__ Bl, int ldb,
    int rowBase, int colBase, int k0, int Nrows, int tid) {
#pragma unroll
    for (int s = 0; s < 4; s++) {
        int idx = tid + s * 256;
        int r = idx >> 3, j = idx & 7;
        int gr = rowBase + r;
        int sz = (gr < Nrows) ? 16 : 0;
        int grc = min(gr, Nrows - 1);
        size_t go = (size_t)grc * lda + k0 + j * 8;
        uint32_t d = smb + r * 144 + j * 16;
        CP16(d,         Ah + go, sz);
        CP16(d + 18432, Al + go, sz);
    }
#pragma unroll
    for (int s = 0; s < 2; s++) {
        int idx = tid + s * 256;
        int n = idx >> 3, j = idx & 7;
        size_t go = (size_t)(colBase + n) * ldb + k0 + j * 8;
        uint32_t d = smb + 36864 + n * 144 + j * 16;
        CP16(d,        Bh + go, 16);
        CP16(d + 9216, Bl + go, 16);
    }
}

// mode 0: fp32 -> Cf (stride LDT, float2)    mode 2: bias+bn+relu -> split bf16x2 pairs
// mode 3: bias -> atomicMax pool
__global__ void __launch_bounds__(256)
k_mma(const __nv_bfloat16* __restrict__ Ah, const __nv_bfloat16* __restrict__ Al, int lda,
      const __nv_bfloat16* __restrict__ Bh, const __nv_bfloat16* __restrict__ Bl, int ldb,
      int Nrows, int Ktiles,
      float* __restrict__ Cf,
      __nv_bfloat16* __restrict__ Oh, __nv_bfloat16* __restrict__ Ol,
      const float* __restrict__ bias, const float* __restrict__ scale,
      const float* __restrict__ shift,
      const int* __restrict__ batch, unsigned* __restrict__ pool, int mode) {
    extern __shared__ __align__(16) char smch[];
    uint32_t sb = smem_u32(smch);

    int tid = threadIdx.x, lane = tid & 31, w = tid >> 5;
    int wm = w & 3, wn = w >> 2;
    int rowBase = blockIdx.y * 128, colBase = blockIdx.x * 64;

    float acc[2][4][4];
#pragma unroll
    for (int i = 0; i < 2; i++)
#pragma unroll
        for (int j = 0; j < 4; j++)
#pragma unroll
            for (int q = 0; q < 4; q++) acc[i][j][q] = 0.f;

    const uint32_t offA = (uint32_t)((wm * 32 + (lane & 15)) * 72 + (lane >> 4) * 8) << 1;
    const uint32_t offB = 36864u +
        ((uint32_t)((wn * 32 + (lane & 7) + ((lane >> 4) << 3)) * 72 + ((lane >> 3) & 1) * 8) << 1);
    const uint32_t A_LO = 18432, B_LO = 9216, MF = 2304;

    ld_stage(sb, Ah, Al, lda, Bh, Bl, ldb, rowBase, colBase, 0, Nrows, tid);
    CP_COMMIT();

    for (int kt = 0; kt < Ktiles; kt++) {
        uint32_t stb = sb + (uint32_t)(kt & 1) * STG;
        if (kt + 1 < Ktiles) {
            ld_stage(sb + (uint32_t)((kt + 1) & 1) * STG, Ah, Al, lda, Bh, Bl, ldb,
                     rowBase, colBase, (kt + 1) * 64, Nrows, tid);
            CP_COMMIT();
            CP_WAIT1();
        } else {
            CP_WAIT0();
        }
        __syncthreads();

        uint32_t aA = stb + offA;
        uint32_t aB = stb + offB;
#pragma unroll
        for (int ks = 0; ks < 4; ks++) {
            uint32_t kso = ks * 32;
            uint32_t bh[4][2], bl[4][2];
            LDSM4(bh[0][0], bh[0][1], bh[1][0], bh[1][1], aB + kso);
            LDSM4(bh[2][0], bh[2][1], bh[3][0], bh[3][1], aB + MF + kso);
            LDSM4(bl[0][0], bl[0][1], bl[1][0], bl[1][1], aB + B_LO + kso);
            LDSM4(bl[2][0], bl[2][1], bl[3][0], bl[3][1], aB + B_LO + MF + kso);
#pragma unroll
            for (int mf = 0; mf < 2; mf++) {
                uint32_t ah[4], al[4];
                LDSM4(ah[0], ah[1], ah[2], ah[3], aA + mf * MF + kso);
                LDSM4(al[0], al[1], al[2], al[3], aA + A_LO + mf * MF + kso);
#pragma unroll
                for (int nf = 0; nf < 4; nf++) {
                    mma16(acc[mf][nf], ah, bh[nf]);
                    mma16(acc[mf][nf], ah, bl[nf]);
                    mma16(acc[mf][nf], al, bh[nf]);
                }
            }
        }
        __syncthreads();
    }

    // epilogue
    int gid = lane >> 2, tig = lane & 3;
#pragma unroll
    for (int mf = 0; mf < 2; mf++) {
#pragma unroll
        for (int half = 0; half < 2; half++) {    // q pair (0,1) at r, (2,3) at r+8
            int r = rowBase + wm * 32 + mf * 16 + gid + half * 8;
            if (r >= Nrows) continue;
            int bidx = (mode == 3) ? batch[r] : 0;
#pragma unroll
            for (int nf = 0; nf < 4; nf++) {
                int c0 = colBase + wn * 32 + nf * 8 + tig * 2;
                float v0 = acc[mf][nf][half * 2];
                float v1 = acc[mf][nf][half * 2 + 1];
                if (mode == 0) {
                    if (c0 < HID)
                        *(float2*)(Cf + (size_t)r * LDT + c0) = make_float2(v0, v1);
                } else if (mode == 2) {
                    float o0 = 0.f, o1 = 0.f;
                    if (c0 < HID)
                        o0 = fmaxf(fmaf(v0 + bias[c0], scale[c0], shift[c0]), 0.f);
                    if (c0 + 1 < HID)
                        o1 = fmaxf(fmaf(v1 + bias[c0 + 1], scale[c0 + 1], shift[c0 + 1]), 0.f);
                    __nv_bfloat16 h0, l0, h1, l1;
                    split_bf(o0, h0, l0);
                    split_bf(o1, h1, l1);
                    size_t di = (size_t)r * LDAH + c0;
                    *(__nv_bfloat162*)(Oh + di) = __nv_bfloat162(h0, h1);
                    *(__nv_bfloat162*)(Ol + di) = __nv_bfloat162(l0, l1);
                } else {
                    if (c0 < HID)
                        atomicMax(&pool[bidx * HID + c0], enc_f(v0 + bias[c0]));
                    if (c0 + 1 < HID)
                        atomicMax(&pool[bidx * HID + c0 + 1], enc_f(v1 + bias[c0 + 1]));
                }
            }
        }
    }
}

// aggregation: gather tmp rows (float2), bias+bn+relu, split-write pairs into concat
__global__ void k_aggregate_h(const float* __restrict__ tmp,
                              const float* __restrict__ bias,
                              const float* __restrict__ scale,
                              const float* __restrict__ shift,
                              int colofs, int N) {
    int n = blockIdx.x;
    int c0 = threadIdx.x * 2;   // 0..190
    float v0 = 0.f, v1 = 0.f;
    if (c0 < HID) {
        int s0 = g_offs[n], s1 = g_offs[n + 1];
        float a0 = 0.f, a1 = 0.f;
        int e = s0;
        for (; e + 2 <= s1; e += 2) {
            int i0 = g_csr_src[e], i1 = g_csr_src[e + 1];
            float w0 = g_csr_w[e], w1 = g_csr_w[e + 1];
            float2 p0 = *(const float2*)(tmp + (size_t)i0 * LDT + c0);
            float2 p1 = *(const float2*)(tmp + (size_t)i1 * LDT + c0);
            a0 += w0 * p0.x + w1 * p1.x;
            a1 += w0 * p0.y + w1 * p1.y;
        }
        if (e < s1) {
            float w = g_csr_w[e];
            float2 p = *(const float2*)(tmp + (size_t)g_csr_src[e] * LDT + c0);
            a0 += w * p.x;
            a1 += w * p.y;
        }
        float dn = g_dis[n];
        float2 self = *(const float2*)(tmp + (size_t)n * LDT + c0);
        v0 = dn * a0 + dn * dn * self.x + bias[c0];
        v0 = fmaxf(fmaf(v0, scale[c0], shift[c0]), 0.f);
        if (c0 + 1 < HID) {
            v1 = dn * a1 + dn * dn * self.y + bias[c0 + 1];
            v1 = fmaxf(fmaf(v1, scale[c0 + 1], shift[c0 + 1]), 0.f);
        }
    }
    __nv_bfloat16 h0, l0, h1, l1;
    split_bf(v0, h0, l0);
    split_bf(v1, h1, l1);
    size_t di = (size_t)n * LDAH + colofs + c0;
    *(__nv_bfloat162*)(g_Ah + di) = __nv_bfloat162(h0, h1);
    *(__nv_bfloat162*)(g_Al + di) = __nv_bfloat162(l0, l1);
}

__global__ void k_finalize(const float* __restrict__ Wout,
                           const float* __restrict__ bout,
                           float* __restrict__ out, int G) {
    int g = blockIdx.x, t = threadIdx.x;
    __shared__ float red[256];
    float p = 0.f;
    for (int c = t; c < HID; c += 256)
        p += dec_f(g_pool[g * HID + c]) * Wout[c];
    red[t] = p;
    __syncthreads();
    for (int o = 128; o; o >>= 1) {
        if (t < o) red[t] += red[t + o];
        __syncthreads();
    }
    if (t == 0) out[g] = red[0] + bout[0];
}

// ---------------- host launcher ----------------
extern "C" void kernel_launch(void* const* d_in, const int* in_sizes, int n_in,
                              void* d_out, int out_size) {
    const float* x     = (const float*)d_in[0];
    const int*   ei    = (const int*)  d_in[1];
    const int*   batch = (const int*)  d_in[2];
    const float* W0    = (const float*)d_in[3];
    const float* b0    = (const float*)d_in[4];
    const float* W_h   = (const float*)d_in[5];
    const float* b_h   = (const float*)d_in[6];
    const float* bn_g  = (const float*)d_in[7];
    const float* bn_b  = (const float*)d_in[8];
    const float* bn_m  = (const float*)d_in[9];
    const float* bn_v  = (const float*)d_in[10];
    const float* W_jk  = (const float*)d_in[11];
    const float* b_jk  = (const float*)d_in[12];
    const float* W_out = (const float*)d_in[13];
    const float* b_out = (const float*)d_in[14];
    float* out = (float*)d_out;

    int N = in_sizes[0] / INCH;
    int E = in_sizes[1] / 2;
    int G = out_size;
    int SB = (N + 255) / 256;

    cudaFuncSetAttribute(k_mma, cudaFuncAttributeMaxDynamicSharedMemorySize, SMEM_BYTES);

    __nv_bfloat16 *a0h, *a0l, *ah, *al, *w0h, *w0l, *whh, *whl, *wjh, *wjl;
    cudaGetSymbolAddress((void**)&a0h, g_A0h);
    cudaGetSymbolAddress((void**)&a0l, g_A0l);
    cudaGetSymbolAddress((void**)&ah,  g_Ah);
    cudaGetSymbolAddress((void**)&al,  g_Al);
    cudaGetSymbolAddress((void**)&w0h, g_W0th);
    cudaGetSymbolAddress((void**)&w0l, g_W0tl);
    cudaGetSymbolAddress((void**)&whh, g_Whth);
    cudaGetSymbolAddress((void**)&whl, g_Whtl);
    cudaGetSymbolAddress((void**)&wjh, g_Wjkth);
    cudaGetSymbolAddress((void**)&wjl, g_Wjktl);
    float *tmp, *bns, *bnh;
    cudaGetSymbolAddress((void**)&tmp, g_tmp);
    cudaGetSymbolAddress((void**)&bns, g_bnscale);
    cudaGetSymbolAddress((void**)&bnh, g_bnshift);
    unsigned* pool;
    cudaGetSymbolAddress((void**)&pool, g_pool);

    int initN = (N > G * HID) ? N : G * HID;
    k_init<<<(initN + 255) / 256, 256>>>(N, G);
    k_count<<<(E + 255) / 256, 256>>>(ei, E);
    k_scan_blk<<<SB, 256>>>(N);
    k_scan_top<<<1, 128>>>(SB);
    k_scan_add<<<SB, 256>>>(N);
    k_fill<<<(E + 255) / 256, 256>>>(ei, E);
    k_aggregate_x<<<(N * 32 + 255) / 256, 256>>>(x, N);
    k_wprep<<<1059, 256>>>(W0, W_h, W_jk, bn_g, bn_b, bn_m, bn_v);

    dim3 grid(3, (N + 127) / 128);

    // layer 0: (Âx)@W0 -> bias+bn0+relu -> split into concat cols [0,192)
    k_mma<<<grid, 256, SMEM_BYTES>>>(a0h, a0l, 64, w0h, w0l, 64, N, 1,
                                     (float*)0, ah, al,
                                     b0, bns, bnh, (const int*)0, (unsigned*)0, 2);
    // hidden layers 1..3
    for (int i = 1; i <= 3; i++) {
        k_mma<<<grid, 256, SMEM_BYTES>>>(ah + (size_t)(i - 1) * 192,
                                         al + (size_t)(i - 1) * 192, LDAH,
                                         whh + (size_t)(i - 1) * 36864,
                                         whl + (size_t)(i - 1) * 36864, 192,
                                         N, 3, tmp,
                                         (__nv_bfloat16*)0, (__nv_bfloat16*)0,
                                         (const float*)0, (const float*)0, (const float*)0,
                                         (const int*)0, (unsigned*)0, 0);
        k_aggregate_h<<<N, 96>>>(tmp, b_h + (size_t)(i - 1) * HID,
                                 bns + i * HID, bnh + i * HID, i * 192, N);
    }
    // JK GEMM fused with max-pool
    k_mma<<<grid, 256, SMEM_BYTES>>>(ah, al, LDAH, wjh, wjl, 768, N, 12,
                                     (float*)0, (__nv_bfloat16*)0, (__nv_bfloat16*)0,
                                     b_jk, (const float*)0, (const float*)0,
                                     batch, pool, 3);

    k_finalize<<<G, 256>>>(W_out, b_out, out, G);
}